// round 1
// baseline (speedup 1.0000x reference)
#include <cuda_runtime.h>

// RC backward-Euler scan, chunked with warm-up.
//
// Reference recurrence (per step k):
//   r0 = Te + dt*b0k ; r1 = Tin + dt*b1k
//   Te'  = (M22k*r0 - M12*r1)/detk
//   Tin' = clip((M11*r1 - M21*r0)/detk, 5, 45)
// Folded affine form (precomputed per step):
//   Te'  = a*Te + b*Tin + h
//   Tin' = clip(d*Tin + e*Te + g)
// with a=M22/det, b=nM12/det, d=M11/det, e=nM21/det,
//      h=a*c0+b*c1, g=d*c1+e*c0, c0=dt*b0, c1=dt*b1.
// Since d = (M11/nM12)*b and e = (nM21/nM12)*b, only {a,b,h,g} are stored
// (16 B/step); the scan derives d,e with two off-chain FMULs.

#define DT_S   1800.0f
#define GA     31.388f      // G*AZ = 0.76*41.3
#define SCHUNK 1024
#define WARM   1280
#define NMAX   (1 << 22)    // 4,194,304

static __device__ float4 g_coeff[NMAX];

__device__ __forceinline__ void step_coeff(
    float To, float Irr, float Qint, float Qah, float Ria,
    float iRie, float iRea, float invCin, float invCen,
    float a_si, float a_se, float a_ii, float a_ie,
    float M11, float nM12, float nM21,
    float4* out)
{
    float Ria_c = fmaxf(Ria, 1e-4f);
    float u     = 1.0f / Ria_c;
    float Irr_c = fminf(fmaxf(Irr, 0.0f), 2000.0f);
    float Qsol  = GA * Irr_c;
    float qah   = fmaxf(Qah, 0.0f);

    float M22 = 1.0f + DT_S * (u + iRie) * invCin;
    float det = M11 * M22 - nM12 * nM21;
    float invdet = 1.0f / det;

    float b0 = To * iRea * invCen + (a_se * Qsol + a_ie * Qint) * invCen;
    float b1 = (To * u + a_si * Qsol + a_ii * Qint + qah) * invCin;
    float c0 = DT_S * b0;
    float c1 = DT_S * b1;

    float a  = M22  * invdet;
    float b  = nM12 * invdet;
    float d  = M11  * invdet;
    float e  = nM21 * invdet;
    float h  = fmaf(a, c0, b * c1);
    float g  = fmaf(d, c1, e * c0);
    *out = make_float4(a, b, h, g);
}

__global__ void __launch_bounds__(256)
pre_kernel(const float* __restrict__ To,  const float* __restrict__ Irr,
           const float* __restrict__ Qint, const float* __restrict__ Qah,
           const float* __restrict__ Ria,
           const float* pR_ie, const float* pR_ea,
           const float* pC_in, const float* pC_en,
           const float* pA_si, const float* pA_se,
           const float* pA_ii, const float* pA_ie,
           int n)
{
    int q = blockIdx.x * blockDim.x + threadIdx.x;
    int i = q * 4;
    if (i >= n) return;

    float iRie   = 1.0f / *pR_ie;
    float iRea   = 1.0f / *pR_ea;
    float invCin = 1.0f / *pC_in;
    float invCen = 1.0f / *pC_en;
    float a_si = *pA_si, a_se = *pA_se, a_ii = *pA_ii, a_ie = *pA_ie;
    float M11  = 1.0f + DT_S * (iRea + iRie) * invCen;
    float nM12 = DT_S * iRie * invCen;
    float nM21 = DT_S * iRie * invCin;

    if (i + 3 < n) {
        float4 to4 = *(const float4*)(To  + i);
        float4 ir4 = *(const float4*)(Irr + i);
        float4 qi4 = *(const float4*)(Qint + i);
        float4 qa4 = *(const float4*)(Qah + i);
        float4 ra4 = *(const float4*)(Ria + i);
        const float* to = (const float*)&to4;
        const float* ir = (const float*)&ir4;
        const float* qi = (const float*)&qi4;
        const float* qa = (const float*)&qa4;
        const float* ra = (const float*)&ra4;
        #pragma unroll
        for (int j = 0; j < 4; ++j) {
            float4 c;
            step_coeff(to[j], ir[j], qi[j], qa[j], ra[j],
                       iRie, iRea, invCin, invCen,
                       a_si, a_se, a_ii, a_ie, M11, nM12, nM21, &c);
            g_coeff[i + j] = c;
        }
    } else {
        for (int j = 0; j < 4 && (i + j) < n; ++j) {
            float4 c;
            step_coeff(To[i+j], Irr[i+j], Qint[i+j], Qah[i+j], Ria[i+j],
                       iRie, iRea, invCin, invCen,
                       a_si, a_se, a_ii, a_ie, M11, nM12, nM21, &c);
            g_coeff[i + j] = c;
        }
    }
}

__global__ void __launch_bounds__(32)
scan_kernel(float* __restrict__ out,
            const float* pR_ie, const float* pR_ea,
            const float* pC_in, const float* pC_en,
            const float* pTin0, int n)
{
    int tid = blockIdx.x * blockDim.x + threadIdx.x;
    long long start = (long long)tid * SCHUNK;
    if (start >= n) return;

    float iRie   = 1.0f / *pR_ie;
    float iRea   = 1.0f / *pR_ea;
    float invCin = 1.0f / *pC_in;
    float invCen = 1.0f / *pC_en;
    float M11  = 1.0f + DT_S * (iRea + iRie) * invCen;
    float nM12 = DT_S * iRie * invCen;
    float nM21 = DT_S * iRie * invCin;
    float kD = M11 / nM12;    // d = kD * b
    float kE = nM21 / nM12;   // e = kE * b  (= C_en/C_in)
    float Tin0 = *pTin0;

    int s   = (int)start;
    int t0  = s - WARM; if (t0 < 0) t0 = 0;   // t0==0 -> carry is EXACT
    int end = s + SCHUNK; if (end > n) end = n;

    float Te = Tin0, Tin = Tin0;

    #pragma unroll 4
    for (int t = t0; t < end; ++t) {
        float4 c = __ldg(&g_coeff[t]);        // {a, b, h, g}
        float dd = kD * c.y;                  // off critical chain
        float ee = kE * c.y;
        float p  = fmaf(c.y, Tin, c.z);       // b*Tin + h
        float q  = fmaf(ee,  Te,  c.w);       // e*Te + g  (Te from prev step, early)
        float Te_n  = fmaf(c.x, Te, p);
        float Tin_n = fmaf(dd, Tin, q);       // critical: FFMA
        Tin_n = fminf(fmaxf(Tin_n, 5.0f), 45.0f);  // + 2x FMNMX = 12 cyc chain
        Te = Te_n; Tin = Tin_n;
        if (t >= s) out[t] = Tin;
    }
}

// Fallback for n > NMAX (shouldn't happen; N is fixed at 2^22): exact
// single-thread sequential scan with on-the-fly coefficients.
__global__ void seq_kernel(const float* __restrict__ To, const float* __restrict__ Irr,
                           const float* __restrict__ Qint, const float* __restrict__ Qah,
                           const float* __restrict__ Ria,
                           const float* pR_ie, const float* pR_ea,
                           const float* pC_in, const float* pC_en,
                           const float* pA_si, const float* pA_se,
                           const float* pA_ii, const float* pA_ie,
                           const float* pTin0,
                           float* __restrict__ out, int n)
{
    float iRie = 1.0f / *pR_ie, iRea = 1.0f / *pR_ea;
    float invCin = 1.0f / *pC_in, invCen = 1.0f / *pC_en;
    float a_si = *pA_si, a_se = *pA_se, a_ii = *pA_ii, a_ie = *pA_ie;
    float M11  = 1.0f + DT_S * (iRea + iRie) * invCen;
    float nM12 = DT_S * iRie * invCen;
    float nM21 = DT_S * iRie * invCin;
    float Te = *pTin0, Tin = *pTin0;
    for (int t = 0; t < n; ++t) {
        float4 c;
        step_coeff(To[t], Irr[t], Qint[t], Qah[t], Ria[t],
                   iRie, iRea, invCin, invCen,
                   a_si, a_se, a_ii, a_ie, M11, nM12, nM21, &c);
        float d = M11 / nM12 * c.y, e = nM21 / nM12 * c.y;
        float Te_n  = fmaf(c.x, Te, fmaf(c.y, Tin, c.z));
        float Tin_n = fmaf(d, Tin, fmaf(e, Te, c.w));
        Tin_n = fminf(fmaxf(Tin_n, 5.0f), 45.0f);
        Te = Te_n; Tin = Tin_n;
        out[t] = Tin;
    }
}

extern "C" void kernel_launch(void* const* d_in, const int* in_sizes, int n_in,
                              void* d_out, int out_size)
{
    const float* pR_ie = (const float*)d_in[0];
    const float* pR_ea = (const float*)d_in[1];
    const float* pC_in = (const float*)d_in[2];
    const float* pC_en = (const float*)d_in[3];
    const float* pA_si = (const float*)d_in[4];
    const float* pA_se = (const float*)d_in[5];
    const float* pA_ii = (const float*)d_in[6];
    const float* pA_ie = (const float*)d_in[7];
    const float* pTin0 = (const float*)d_in[8];
    const float* To   = (const float*)d_in[9];
    const float* Irr  = (const float*)d_in[10];
    const float* Qint = (const float*)d_in[11];
    const float* Qah  = (const float*)d_in[12];
    const float* Ria  = (const float*)d_in[13];
    float* out = (float*)d_out;
    int n = in_sizes[9];

    if (n > NMAX) {
        seq_kernel<<<1, 1>>>(To, Irr, Qint, Qah, Ria,
                             pR_ie, pR_ea, pC_in, pC_en,
                             pA_si, pA_se, pA_ii, pA_ie, pTin0, out, n);
        return;
    }

    int quads = (n + 3) / 4;
    pre_kernel<<<(quads + 255) / 256, 256>>>(
        To, Irr, Qint, Qah, Ria,
        pR_ie, pR_ea, pC_in, pC_en, pA_si, pA_se, pA_ii, pA_ie, n);

    int chunks = (n + SCHUNK - 1) / SCHUNK;
    scan_kernel<<<(chunks + 31) / 32, 32>>>(
        out, pR_ie, pR_ea, pC_in, pC_en, pTin0, n);
}

// round 2
// speedup vs baseline: 3.4627x; 3.4627x over previous
#include <cuda_runtime.h>

// RC backward-Euler scan, chunked + warm-up, transposed coefficients,
// register ping-pong prefetch (distance 16).
//
// Folded affine per-step map (precomputed):
//   Te'  = a*Te + b*Tin + h
//   Tin' = clip(d*Tin + e*Te + g, 5, 45),  d = kD*b, e = kE*b (constants)
// Stored per step: {a, b, h, g} = 16 B, in TRANSPOSED layout
//   coeff[(k % S) * C + (k / S)]  (k = global timestep, C = n/S chunks)
// so a warp of 32 adjacent chunks reads one coalesced 512B line per step.

#define DT_S   1800.0f
#define GA     31.388f          // G*AZ = 0.76*41.3
#define S2     512              // steps per chunk
#define PWARM  2                // warm-up = PWARM whole chunks (W = 1024)
#define NMAX   (1 << 22)

static __device__ float4 g_coeff[NMAX];

// ---------------------------------------------------------------- coeff math
__device__ __forceinline__ float4 step_coeff(
    float To, float Irr, float Qint, float Qah, float Ria,
    float iRie, float iRea, float invCin, float invCen,
    float a_si, float a_se, float a_ii, float a_ie,
    float M11, float nM12, float nM21)
{
    float Ria_c = fmaxf(Ria, 1e-4f);
    float u     = 1.0f / Ria_c;
    float Irr_c = fminf(fmaxf(Irr, 0.0f), 2000.0f);
    float Qsol  = GA * Irr_c;
    float qah   = fmaxf(Qah, 0.0f);

    float M22 = 1.0f + DT_S * (u + iRie) * invCin;
    float det = M11 * M22 - nM12 * nM21;
    float invdet = 1.0f / det;

    float b0 = To * iRea * invCen + (a_se * Qsol + a_ie * Qint) * invCen;
    float b1 = (To * u + a_si * Qsol + a_ii * Qint + qah) * invCin;
    float c0 = DT_S * b0;
    float c1 = DT_S * b1;

    float a = M22  * invdet;
    float b = nM12 * invdet;
    float d = M11  * invdet;
    float e = nM21 * invdet;
    float h = fmaf(a, c0, b * c1);
    float g = fmaf(d, c1, e * c0);
    return make_float4(a, b, h, g);
}

// ------------------------------------------- pre-pass: compute + transpose
// Block = 1024 threads handling a 32(k) x 32(j) tile.
// Read phase : warp reads 32 consecutive timesteps  (coalesced 128B x5)
// Write phase: warp writes 32 consecutive chunks of one k-row (coalesced 512B)
__global__ void __launch_bounds__(1024)
pre_t_kernel(const float* __restrict__ To,  const float* __restrict__ Irr,
             const float* __restrict__ Qint, const float* __restrict__ Qah,
             const float* __restrict__ Ria,
             const float* pR_ie, const float* pR_ea,
             const float* pC_in, const float* pC_en,
             const float* pA_si, const float* pA_se,
             const float* pA_ii, const float* pA_ie,
             int C)
{
    __shared__ float4 tile[32][33];

    float iRie   = 1.0f / *pR_ie;
    float iRea   = 1.0f / *pR_ea;
    float invCin = 1.0f / *pC_in;
    float invCen = 1.0f / *pC_en;
    float a_si = *pA_si, a_se = *pA_se, a_ii = *pA_ii, a_ie = *pA_ie;
    float M11  = 1.0f + DT_S * (iRea + iRie) * invCen;
    float nM12 = DT_S * iRie * invCen;
    float nM21 = DT_S * iRie * invCin;

    int j0 = blockIdx.x * 32;
    int k0 = blockIdx.y * 32;

    {   // read + compute
        int kk = threadIdx.x & 31;
        int jj = threadIdx.x >> 5;
        int t  = (j0 + jj) * S2 + (k0 + kk);
        tile[kk][jj] = step_coeff(__ldg(To + t), __ldg(Irr + t), __ldg(Qint + t),
                                  __ldg(Qah + t), __ldg(Ria + t),
                                  iRie, iRea, invCin, invCen,
                                  a_si, a_se, a_ii, a_ie, M11, nM12, nM21);
    }
    __syncthreads();
    {   // transposed write
        int jj = threadIdx.x & 31;
        int kk = threadIdx.x >> 5;
        g_coeff[(k0 + kk) * C + (j0 + jj)] = tile[kk][jj];
    }
}

// ------------------------------------------------------------- scan kernel
template<bool OUT>
__device__ __forceinline__ void process16(
    const float4* __restrict__ buf,
    float& Te, float& Tin, float kD, float kE,
    float* __restrict__ outp)
{
    float t0 = 0.f, t1 = 0.f, t2 = 0.f;
    #pragma unroll
    for (int u = 0; u < 16; ++u) {
        float4 c = buf[u];
        float dd = kD * c.y;
        float ee = kE * c.y;
        float p  = fmaf(c.y, Tin, c.z);
        float q  = fmaf(ee,  Te,  c.w);
        float Te_n  = fmaf(c.x, Te, p);
        float Tin_n = fmaf(dd, Tin, q);
        Tin_n = fminf(fmaxf(Tin_n, 5.0f), 45.0f);
        Te = Te_n; Tin = Tin_n;
        if (OUT) {
            int r = u & 3;
            if (r == 0)      t0 = Tin;
            else if (r == 1) t1 = Tin;
            else if (r == 2) t2 = Tin;
            else  *(float4*)(outp + (u - 3)) = make_float4(t0, t1, t2, Tin);
        }
    }
}

__global__ void __launch_bounds__(32)
scan_t_kernel(float* __restrict__ out,
              const float* pR_ie, const float* pR_ea,
              const float* pC_in, const float* pC_en,
              const float* pTin0, int C)
{
    int j = blockIdx.x * 32 + threadIdx.x;
    if (j >= C) return;

    float iRie   = 1.0f / *pR_ie;
    float iRea   = 1.0f / *pR_ea;
    float invCin = 1.0f / *pC_in;
    float invCen = 1.0f / *pC_en;
    float M11  = 1.0f + DT_S * (iRea + iRie) * invCen;
    float nM12 = DT_S * iRie * invCen;
    float nM21 = DT_S * iRie * invCin;
    float kD = M11  / nM12;
    float kE = nM21 / nM12;
    float Tin0 = *pTin0;

    float Te = Tin0, Tin = Tin0;

    #pragma unroll 1
    for (int seg = 0; seg <= PWARM; ++seg) {
        int col = j - PWARM + seg;
        if (col < 0) continue;                 // truncated warm-up: exact from t=0
        const float4* __restrict__ p = g_coeff + col;   // row k at p[k*C]
        bool isOut = (seg == PWARM);
        float* outp = out + j * S2;

        float4 A[16], B[16];
        #pragma unroll
        for (int u = 0; u < 16; ++u) A[u] = __ldg(p + u * C);

        #pragma unroll 1
        for (int kt = 0; kt < S2; kt += 32) {
            // prefetch rows kt+16..kt+31 while computing kt..kt+15
            #pragma unroll
            for (int u = 0; u < 16; ++u) B[u] = __ldg(p + (kt + 16 + u) * C);

            if (isOut) process16<true >(A, Te, Tin, kD, kE, outp + kt);
            else       process16<false>(A, Te, Tin, kD, kE, nullptr);

            // prefetch rows kt+32..kt+47 while computing kt+16..kt+31
            if (kt + 32 < S2) {
                #pragma unroll
                for (int u = 0; u < 16; ++u) A[u] = __ldg(p + (kt + 32 + u) * C);
            }
            if (isOut) process16<true >(B, Te, Tin, kD, kE, outp + kt + 16);
            else       process16<false>(B, Te, Tin, kD, kE, nullptr);
        }
    }
}

// ------------------------------------------- exact fallback (ragged n only)
__global__ void seq_kernel(const float* __restrict__ To, const float* __restrict__ Irr,
                           const float* __restrict__ Qint, const float* __restrict__ Qah,
                           const float* __restrict__ Ria,
                           const float* pR_ie, const float* pR_ea,
                           const float* pC_in, const float* pC_en,
                           const float* pA_si, const float* pA_se,
                           const float* pA_ii, const float* pA_ie,
                           const float* pTin0,
                           float* __restrict__ out, int n)
{
    float iRie = 1.0f / *pR_ie, iRea = 1.0f / *pR_ea;
    float invCin = 1.0f / *pC_in, invCen = 1.0f / *pC_en;
    float a_si = *pA_si, a_se = *pA_se, a_ii = *pA_ii, a_ie = *pA_ie;
    float M11  = 1.0f + DT_S * (iRea + iRie) * invCen;
    float nM12 = DT_S * iRie * invCen;
    float nM21 = DT_S * iRie * invCin;
    float kD = M11 / nM12, kE = nM21 / nM12;
    float Te = *pTin0, Tin = *pTin0;
    for (int t = 0; t < n; ++t) {
        float4 c = step_coeff(To[t], Irr[t], Qint[t], Qah[t], Ria[t],
                              iRie, iRea, invCin, invCen,
                              a_si, a_se, a_ii, a_ie, M11, nM12, nM21);
        float d = kD * c.y, e = kE * c.y;
        float Te_n  = fmaf(c.x, Te, fmaf(c.y, Tin, c.z));
        float Tin_n = fmaf(d, Tin, fmaf(e, Te, c.w));
        Tin_n = fminf(fmaxf(Tin_n, 5.0f), 45.0f);
        Te = Te_n; Tin = Tin_n;
        out[t] = Tin;
    }
}

extern "C" void kernel_launch(void* const* d_in, const int* in_sizes, int n_in,
                              void* d_out, int out_size)
{
    const float* pR_ie = (const float*)d_in[0];
    const float* pR_ea = (const float*)d_in[1];
    const float* pC_in = (const float*)d_in[2];
    const float* pC_en = (const float*)d_in[3];
    const float* pA_si = (const float*)d_in[4];
    const float* pA_se = (const float*)d_in[5];
    const float* pA_ii = (const float*)d_in[6];
    const float* pA_ie = (const float*)d_in[7];
    const float* pTin0 = (const float*)d_in[8];
    const float* To   = (const float*)d_in[9];
    const float* Irr  = (const float*)d_in[10];
    const float* Qint = (const float*)d_in[11];
    const float* Qah  = (const float*)d_in[12];
    const float* Ria  = (const float*)d_in[13];
    float* out = (float*)d_out;
    int n = in_sizes[9];

    if (n > NMAX || n <= 0 || (n % S2) != 0 || (n / S2) % 32 != 0) {
        seq_kernel<<<1, 1>>>(To, Irr, Qint, Qah, Ria,
                             pR_ie, pR_ea, pC_in, pC_en,
                             pA_si, pA_se, pA_ii, pA_ie, pTin0, out, n);
        return;
    }

    int C = n / S2;                       // 8192 chunks for n = 2^22
    dim3 pgrid(C / 32, S2 / 32);          // (256, 16) blocks of 1024
    pre_t_kernel<<<pgrid, 1024>>>(To, Irr, Qint, Qah, Ria,
                                  pR_ie, pR_ea, pC_in, pC_en,
                                  pA_si, pA_se, pA_ii, pA_ie, C);

    scan_t_kernel<<<C / 32, 32>>>(out, pR_ie, pR_ea, pC_in, pC_en, pTin0, C);
}

// round 3
// speedup vs baseline: 3.5654x; 1.0297x over previous
#include <cuda_runtime.h>

// RC backward-Euler scan. v3:
//  - setup kernel hoists all derived constants (no per-thread divides)
//  - pre-pass: ONE batched reciprocal per 4 elements (ip = 1/(gamma*Ria+delta),
//    invdet = Ria*ip, u*invdet = ip), stores {b,h,g} 12 B/step in 3 float4-
//    packed transposed planes  plane[(k/4)*C + chunk]
//  - scan: S=256, warm-up 768, 128-thread blocks (warps spread over 4 SMSPs),
//    16-step register double-buffer, a/d/e derived from b (affine/scaled)

#define DT_S   1800.0f
#define GA     31.388f
#define S2     256
#define PWARM  3                 // warm-up = 3 chunks = 768 steps
#define NMAX   (1 << 22)

static __device__ float4 g_b4[NMAX / 4];
static __device__ float4 g_h4[NMAX / 4];
static __device__ float4 g_g4[NMAX / 4];

struct Consts {
    float iRie, iRea, invCin, invCen;
    float M11, nM12, nM21;
    float kD, kE;          // d = kD*b, e = kE*b
    float k0a, k1a;        // a  = k0a + k1a*b
    float gam, del;        // P  = gam*Ria + del, ip = 1/P
    float c_h, c_g1;       // h += c_h*T1 ; g = c_g1*T1 + nM21*rp*s0
    float dtCen;           // dt/C_en
    float a_si, a_se, a_ii, a_ie;
    float Tin0;
};
static __device__ Consts g_cst;

__global__ void setup_kernel(const float* pR_ie, const float* pR_ea,
                             const float* pC_in, const float* pC_en,
                             const float* pA_si, const float* pA_se,
                             const float* pA_ii, const float* pA_ie,
                             const float* pTin0)
{
    if (threadIdx.x != 0) return;
    Consts c;
    c.iRie   = 1.0f / *pR_ie;
    c.iRea   = 1.0f / *pR_ea;
    c.invCin = 1.0f / *pC_in;
    c.invCen = 1.0f / *pC_en;
    c.M11  = 1.0f + DT_S * (c.iRea + c.iRie) * c.invCen;
    c.nM12 = DT_S * c.iRie * c.invCen;
    c.nM21 = DT_S * c.iRie * c.invCin;
    c.kD   = c.M11  / c.nM12;
    c.kE   = c.nM21 / c.nM12;
    c.k0a  = 1.0f / c.M11;
    c.k1a  = c.nM21 / c.M11;
    float alpha = 1.0f + DT_S * c.iRie * c.invCin;   // M22 = alpha + beta*u
    float beta  = DT_S * c.invCin;
    c.gam  = c.M11 * alpha - c.nM12 * c.nM21;        // det = gam + del*u
    c.del  = c.M11 * beta;
    c.c_h  = c.nM12 * DT_S * c.invCin;
    c.c_g1 = c.M11  * DT_S * c.invCin;
    c.dtCen = DT_S * c.invCen;
    c.a_si = *pA_si; c.a_se = *pA_se; c.a_ii = *pA_ii; c.a_ie = *pA_ie;
    c.Tin0 = *pTin0;
    g_cst = c;
}

__device__ __forceinline__ float frcp_approx(float x) {
    float r;
    asm("rcp.approx.f32 %0, %1;" : "=f"(r) : "f"(x));
    return r;
}

// ------------------------------------------- pre-pass: compute + transpose
// 256-thread block handles a 32(k) x 32(j) tile; each thread computes 4
// consecutive timesteps (one batched reciprocal serves all 4).
__global__ void __launch_bounds__(256)
pre_t_kernel(const float* __restrict__ To,  const float* __restrict__ Irr,
             const float* __restrict__ Qint, const float* __restrict__ Qah,
             const float* __restrict__ Ria, int C)
{
    __shared__ float sb[32][33], sh[32][33], sg[32][33];
    const Consts c = g_cst;

    int j0 = blockIdx.x * 32;
    int k0 = blockIdx.y * 32;

    {   // phase 1: read (coalesced 128B runs) + compute
        int kg = threadIdx.x & 7;        // 0..7 (x4 steps)
        int jj = threadIdx.x >> 3;       // 0..31
        int t  = (j0 + jj) * S2 + k0 + 4 * kg;

        float4 to4 = *(const float4*)(To  + t);
        float4 ir4 = *(const float4*)(Irr + t);
        float4 qi4 = *(const float4*)(Qint + t);
        float4 qa4 = *(const float4*)(Qah + t);
        float4 ra4 = *(const float4*)(Ria + t);
        const float* to = (const float*)&to4;
        const float* ir = (const float*)&ir4;
        const float* qi = (const float*)&qi4;
        const float* qa = (const float*)&qa4;
        const float* ra = (const float*)&ra4;

        // batched reciprocal of P_i = gam*Ria_c + del
        float Rc[4], P[4], ipv[4];
        #pragma unroll
        for (int i = 0; i < 4; ++i) {
            Rc[i] = fmaxf(ra[i], 1e-4f);
            P[i]  = fmaf(c.gam, Rc[i], c.del);
        }
        float p01 = P[0] * P[1], p23 = P[2] * P[3];
        float ipa = frcp_approx(p01 * p23);
        float i01 = ipa * p23, i23 = ipa * p01;
        ipv[0] = i01 * P[1]; ipv[1] = i01 * P[0];
        ipv[2] = i23 * P[3]; ipv[3] = i23 * P[2];
        #pragma unroll
        for (int i = 0; i < 4; ++i)   // one Newton polish
            ipv[i] = ipv[i] * fmaf(-P[i], ipv[i], 2.0f);

        #pragma unroll
        for (int i = 0; i < 4; ++i) {
            float ip  = ipv[i];
            float rp  = Rc[i] * ip;                 // invdet
            float Qs  = GA * fminf(fmaxf(ir[i], 0.0f), 2000.0f);
            float qh  = fmaxf(qa[i], 0.0f);
            float b   = c.nM12 * rp;
            float a   = fmaf(c.k1a, b, c.k0a);
            float s0  = c.dtCen * fmaf(to[i], c.iRea,
                                 fmaf(c.a_se, Qs, c.a_ie * qi[i]));
            float s1  = fmaf(c.a_si, Qs, fmaf(c.a_ii, qi[i], qh));
            float T1  = ip * fmaf(Rc[i], s1, to[i]);
            float h   = fmaf(c.c_h, T1, a * s0);
            float g   = fmaf(c.c_g1, T1, c.nM21 * (rp * s0));
            int k = 4 * kg + i;
            sb[k][jj] = b; sh[k][jj] = h; sg[k][jj] = g;
        }
    }
    __syncthreads();
    {   // phase 2: transposed float4-packed writes (coalesced 512B)
        int jj = threadIdx.x & 31;
        int kg = threadIdx.x >> 5;       // 0..7
        int row = (k0 >> 2) + kg;        // global kgroup
        int idx = row * C + j0 + jj;
        g_b4[idx] = make_float4(sb[4*kg][jj], sb[4*kg+1][jj], sb[4*kg+2][jj], sb[4*kg+3][jj]);
        g_h4[idx] = make_float4(sh[4*kg][jj], sh[4*kg+1][jj], sh[4*kg+2][jj], sh[4*kg+3][jj]);
        g_g4[idx] = make_float4(sg[4*kg][jj], sg[4*kg+1][jj], sg[4*kg+2][jj], sg[4*kg+3][jj]);
    }
}

// ------------------------------------------------------------- scan kernel
struct G16 { float4 b[4], h[4], g[4]; };

__device__ __forceinline__ void load16(G16& d, int kgBase, int col, int C) {
    #pragma unroll
    for (int i = 0; i < 4; ++i) {
        int idx = (kgBase + i) * C + col;
        d.b[i] = __ldg(&g_b4[idx]);
        d.h[i] = __ldg(&g_h4[idx]);
        d.g[i] = __ldg(&g_g4[idx]);
    }
}

template<bool OUT>
__device__ __forceinline__ void process16(
    const G16& d, float& Te, float& Tin,
    float kD, float kE, float k0a, float k1a,
    float* __restrict__ outp)
{
    #pragma unroll
    for (int i = 0; i < 4; ++i) {
        const float* bb = (const float*)&d.b[i];
        const float* hh = (const float*)&d.h[i];
        const float* gg = (const float*)&d.g[i];
        float4 v;
        float* vv = (float*)&v;
        #pragma unroll
        for (int e = 0; e < 4; ++e) {
            float b = bb[e];
            float a  = fmaf(k1a, b, k0a);
            float dd = kD * b;
            float ee = kE * b;
            float p  = fmaf(b,  Tin, hh[e]);
            float q  = fmaf(ee, Te,  gg[e]);
            float Te_n  = fmaf(a,  Te,  p);
            float Tin_n = fmaf(dd, Tin, q);
            Tin_n = fminf(fmaxf(Tin_n, 5.0f), 45.0f);
            Te = Te_n; Tin = Tin_n;
            if (OUT) vv[e] = Tin;
        }
        if (OUT) *(float4*)(outp + 4 * i) = v;
    }
}

__global__ void __launch_bounds__(128)
scan_t_kernel(float* __restrict__ out, int C)
{
    int j = blockIdx.x * 128 + threadIdx.x;
    if (j >= C) return;
    const Consts c = g_cst;
    float kD = c.kD, kE = c.kE, k0a = c.k0a, k1a = c.k1a;

    float Te = c.Tin0, Tin = c.Tin0;

    #pragma unroll 1
    for (int seg = 0; seg <= PWARM; ++seg) {
        int col = j - PWARM + seg;
        if (col < 0) continue;               // truncated warm-up: exact from t=0
        bool isOut = (seg == PWARM);
        float* outp = out + j * S2;

        G16 A, B;
        load16(A, 0, col, C);

        #pragma unroll 1
        for (int kt = 0; kt < S2; kt += 32) {
            int kg = kt >> 2;
            load16(B, kg + 4, col, C);
            if (isOut) process16<true >(A, Te, Tin, kD, kE, k0a, k1a, outp + kt);
            else       process16<false>(A, Te, Tin, kD, kE, k0a, k1a, nullptr);
            if (kt + 32 < S2) load16(A, kg + 8, col, C);
            if (isOut) process16<true >(B, Te, Tin, kD, kE, k0a, k1a, outp + kt + 16);
            else       process16<false>(B, Te, Tin, kD, kE, k0a, k1a, nullptr);
        }
    }
}

// ------------------------------------------- exact fallback (ragged n only)
__global__ void seq_kernel(const float* __restrict__ To, const float* __restrict__ Irr,
                           const float* __restrict__ Qint, const float* __restrict__ Qah,
                           const float* __restrict__ Ria,
                           const float* pR_ie, const float* pR_ea,
                           const float* pC_in, const float* pC_en,
                           const float* pA_si, const float* pA_se,
                           const float* pA_ii, const float* pA_ie,
                           const float* pTin0,
                           float* __restrict__ out, int n)
{
    float iRie = 1.0f / *pR_ie, iRea = 1.0f / *pR_ea;
    float invCin = 1.0f / *pC_in, invCen = 1.0f / *pC_en;
    float a_si = *pA_si, a_se = *pA_se, a_ii = *pA_ii, a_ie = *pA_ie;
    float M11  = 1.0f + DT_S * (iRea + iRie) * invCen;
    float nM12 = DT_S * iRie * invCen;
    float nM21 = DT_S * iRie * invCin;
    float Te = *pTin0, Tin = *pTin0;
    for (int t = 0; t < n; ++t) {
        float Ria_c = fmaxf(Ria[t], 1e-4f);
        float u     = 1.0f / Ria_c;
        float Qsol  = GA * fminf(fmaxf(Irr[t], 0.0f), 2000.0f);
        float qah   = fmaxf(Qah[t], 0.0f);
        float M22 = 1.0f + DT_S * (u + iRie) * invCin;
        float det = M11 * M22 - nM12 * nM21;
        float invdet = 1.0f / det;
        float b0 = To[t] * iRea * invCen + (a_se * Qsol + a_ie * Qint[t]) * invCen;
        float b1 = (To[t] * u + a_si * Qsol + a_ii * Qint[t] + qah) * invCin;
        float r0 = Te + DT_S * b0;
        float r1 = Tin + DT_S * b1;
        float Te_n  = (M22 * r0 + nM12 * r1) * invdet;
        float Tin_n = (M11 * r1 + nM21 * r0) * invdet;
        Tin_n = fminf(fmaxf(Tin_n, 5.0f), 45.0f);
        Te = Te_n; Tin = Tin_n;
        out[t] = Tin_n;
    }
}

extern "C" void kernel_launch(void* const* d_in, const int* in_sizes, int n_in,
                              void* d_out, int out_size)
{
    const float* pR_ie = (const float*)d_in[0];
    const float* pR_ea = (const float*)d_in[1];
    const float* pC_in = (const float*)d_in[2];
    const float* pC_en = (const float*)d_in[3];
    const float* pA_si = (const float*)d_in[4];
    const float* pA_se = (const float*)d_in[5];
    const float* pA_ii = (const float*)d_in[6];
    const float* pA_ie = (const float*)d_in[7];
    const float* pTin0 = (const float*)d_in[8];
    const float* To   = (const float*)d_in[9];
    const float* Irr  = (const float*)d_in[10];
    const float* Qint = (const float*)d_in[11];
    const float* Qah  = (const float*)d_in[12];
    const float* Ria  = (const float*)d_in[13];
    float* out = (float*)d_out;
    int n = in_sizes[9];

    if (n > NMAX || n <= 0 || (n % S2) != 0 || ((n / S2) % 128) != 0) {
        seq_kernel<<<1, 1>>>(To, Irr, Qint, Qah, Ria,
                             pR_ie, pR_ea, pC_in, pC_en,
                             pA_si, pA_se, pA_ii, pA_ie, pTin0, out, n);
        return;
    }

    setup_kernel<<<1, 32>>>(pR_ie, pR_ea, pC_in, pC_en,
                            pA_si, pA_se, pA_ii, pA_ie, pTin0);

    int C = n / S2;                          // 16384
    dim3 pgrid(C / 32, S2 / 32);             // (512, 8) blocks of 256
    pre_t_kernel<<<pgrid, 256>>>(To, Irr, Qint, Qah, Ria, C);

    scan_t_kernel<<<C / 128, 128>>>(out, C);
}

// round 4
// speedup vs baseline: 5.8917x; 1.6525x over previous
#include <cuda_runtime.h>
#include <cuda_fp16.h>

// RC backward-Euler scan. v4:
//  - no setup kernel: every thread derives constants from the scalar inputs
//  - coefficients 8 B/step: b (fp32) + (h,g) packed __half2
//    planes transposed & float4-packed:  plane[(k/4)*C + chunk]
//  - S=256, warm-up = 2 chunks (512 steps; clip-saturation resets carry error)
//  - scan: 128-thread blocks, 16-step register double-buffer

#define DT_S   1800.0f
#define GA     31.388f
#define S2     256
#define PWARM  2
#define NMAX   (1 << 22)

static __device__ float4 g_b4[NMAX / 4];    // 4 steps of b per entry
static __device__ uint4  g_hg4[NMAX / 4];   // 4 steps of packed (h,g) per entry

struct DCst {
    float iRie, iRea, invCin, invCen;
    float M11, nM12, nM21;
    float kD, kE, k0a, k1a;
    float gam, del, c_h, c_g1, dtCen;
};

__device__ __forceinline__ DCst make_consts(float R_ie, float R_ea,
                                            float C_in, float C_en)
{
    DCst c;
    c.iRie   = 1.0f / R_ie;
    c.iRea   = 1.0f / R_ea;
    c.invCin = 1.0f / C_in;
    c.invCen = 1.0f / C_en;
    c.M11  = 1.0f + DT_S * (c.iRea + c.iRie) * c.invCen;
    c.nM12 = DT_S * c.iRie * c.invCen;
    c.nM21 = DT_S * c.iRie * c.invCin;
    c.kD   = c.M11  / c.nM12;
    c.kE   = c.nM21 / c.nM12;
    c.k0a  = 1.0f / c.M11;
    c.k1a  = c.nM21 / c.M11;
    float alpha = 1.0f + DT_S * c.iRie * c.invCin;   // M22 = alpha + beta*u
    float beta  = DT_S * c.invCin;
    c.gam  = c.M11 * alpha - c.nM12 * c.nM21;        // det = gam + del*u
    c.del  = c.M11 * beta;
    c.c_h  = c.nM12 * DT_S * c.invCin;
    c.c_g1 = c.M11  * DT_S * c.invCin;
    c.dtCen = DT_S * c.invCen;
    return c;
}

__device__ __forceinline__ float frcp_approx(float x) {
    float r;
    asm("rcp.approx.f32 %0, %1;" : "=f"(r) : "f"(x));
    return r;
}

// ------------------------------------------- pre-pass: compute + transpose
// 256-thread block: 32(k) x 32(j) tile, each thread does 4 consecutive steps
// (one batched reciprocal per 4 elements).
__global__ void __launch_bounds__(256)
pre_t_kernel(const float* __restrict__ To,  const float* __restrict__ Irr,
             const float* __restrict__ Qint, const float* __restrict__ Qah,
             const float* __restrict__ Ria,
             const float* pR_ie, const float* pR_ea,
             const float* pC_in, const float* pC_en,
             const float* pA_si, const float* pA_se,
             const float* pA_ii, const float* pA_ie,
             int C)
{
    __shared__ float4 tb[8][33];
    __shared__ uint4  th[8][33];

    const DCst c = make_consts(__ldg(pR_ie), __ldg(pR_ea), __ldg(pC_in), __ldg(pC_en));
    float a_si = __ldg(pA_si), a_se = __ldg(pA_se);
    float a_ii = __ldg(pA_ii), a_ie = __ldg(pA_ie);

    int j0 = blockIdx.x * 32;
    int k0 = blockIdx.y * 32;

    {   // phase 1: coalesced read + compute
        int kg = threadIdx.x & 7;        // 0..7 (x4 steps)
        int jj = threadIdx.x >> 3;       // 0..31
        int t  = (j0 + jj) * S2 + k0 + 4 * kg;

        float4 to4 = *(const float4*)(To  + t);
        float4 ir4 = *(const float4*)(Irr + t);
        float4 qi4 = *(const float4*)(Qint + t);
        float4 qa4 = *(const float4*)(Qah + t);
        float4 ra4 = *(const float4*)(Ria + t);
        const float* to = (const float*)&to4;
        const float* ir = (const float*)&ir4;
        const float* qi = (const float*)&qi4;
        const float* qa = (const float*)&qa4;
        const float* ra = (const float*)&ra4;

        float Rc[4], P[4], ipv[4];
        #pragma unroll
        for (int i = 0; i < 4; ++i) {
            Rc[i] = fmaxf(ra[i], 1e-4f);
            P[i]  = fmaf(c.gam, Rc[i], c.del);
        }
        float p01 = P[0] * P[1], p23 = P[2] * P[3];
        float ipa = frcp_approx(p01 * p23);
        float i01 = ipa * p23, i23 = ipa * p01;
        ipv[0] = i01 * P[1]; ipv[1] = i01 * P[0];
        ipv[2] = i23 * P[3]; ipv[3] = i23 * P[2];
        #pragma unroll
        for (int i = 0; i < 4; ++i)      // one Newton polish
            ipv[i] = ipv[i] * fmaf(-P[i], ipv[i], 2.0f);

        float4 b4;  float* bp = (float*)&b4;
        uint4  hg4; unsigned* hp = (unsigned*)&hg4;
        #pragma unroll
        for (int i = 0; i < 4; ++i) {
            float ip  = ipv[i];
            float rp  = Rc[i] * ip;                 // invdet
            float Qs  = GA * fminf(fmaxf(ir[i], 0.0f), 2000.0f);
            float qh  = fmaxf(qa[i], 0.0f);
            float b   = c.nM12 * rp;
            float a   = fmaf(c.k1a, b, c.k0a);
            float s0  = c.dtCen * fmaf(to[i], c.iRea,
                                 fmaf(a_se, Qs, a_ie * qi[i]));
            float s1  = fmaf(a_si, Qs, fmaf(a_ii, qi[i], qh));
            float T1  = ip * fmaf(Rc[i], s1, to[i]);
            float h   = fmaf(c.c_h, T1, a * s0);
            float g   = fmaf(c.c_g1, T1, c.nM21 * (rp * s0));
            bp[i] = b;
            __half2 p = __floats2half2_rn(h, g);
            hp[i] = *reinterpret_cast<unsigned*>(&p);
        }
        tb[kg][jj] = b4;
        th[kg][jj] = hg4;
    }
    __syncthreads();
    {   // phase 2: transposed coalesced 512B writes
        int jj = threadIdx.x & 31;
        int kg = threadIdx.x >> 5;       // 0..7
        int idx = ((k0 >> 2) + kg) * C + j0 + jj;
        g_b4[idx]  = tb[kg][jj];
        g_hg4[idx] = th[kg][jj];
    }
}

// ------------------------------------------------------------- scan kernel
struct G16 { float4 b[4]; uint4 hg[4]; };

__device__ __forceinline__ void load16(G16& d, int kgBase, int col, int C) {
    #pragma unroll
    for (int i = 0; i < 4; ++i) {
        int idx = (kgBase + i) * C + col;
        d.b[i]  = __ldg(&g_b4[idx]);
        d.hg[i] = __ldg(&g_hg4[idx]);
    }
}

template<bool OUT>
__device__ __forceinline__ void process16(
    const G16& d, float& Te, float& Tin,
    float kD, float kE, float k0a, float k1a,
    float* __restrict__ outp)
{
    #pragma unroll
    for (int i = 0; i < 4; ++i) {
        const float*    bb = (const float*)&d.b[i];
        const unsigned* hh = (const unsigned*)&d.hg[i];
        float4 v;
        float* vv = (float*)&v;
        #pragma unroll
        for (int e = 0; e < 4; ++e) {
            float b = bb[e];
            unsigned hgu = hh[e];
            __half2 hg2 = *reinterpret_cast<const __half2*>(&hgu);
            float2 hg = __half22float2(hg2);
            float a  = fmaf(k1a, b, k0a);
            float dd = kD * b;
            float ee = kE * b;
            float p  = fmaf(b,  Tin, hg.x);
            float q  = fmaf(ee, Te,  hg.y);
            float Te_n  = fmaf(a,  Te,  p);
            float Tin_n = fmaf(dd, Tin, q);
            Tin_n = fminf(fmaxf(Tin_n, 5.0f), 45.0f);
            Te = Te_n; Tin = Tin_n;
            if (OUT) vv[e] = Tin;
        }
        if (OUT) *(float4*)(outp + 4 * i) = v;
    }
}

__global__ void __launch_bounds__(128)
scan_t_kernel(float* __restrict__ out,
              const float* pR_ie, const float* pR_ea,
              const float* pC_in, const float* pC_en,
              const float* pTin0, int C)
{
    int j = blockIdx.x * 128 + threadIdx.x;
    if (j >= C) return;

    const DCst c = make_consts(__ldg(pR_ie), __ldg(pR_ea), __ldg(pC_in), __ldg(pC_en));
    float kD = c.kD, kE = c.kE, k0a = c.k0a, k1a = c.k1a;
    float Tin0 = __ldg(pTin0);

    float Te = Tin0, Tin = Tin0;

    #pragma unroll 1
    for (int seg = 0; seg <= PWARM; ++seg) {
        int col = j - PWARM + seg;
        if (col < 0) continue;               // truncated warm-up: exact from t=0
        bool isOut = (seg == PWARM);
        float* outp = out + j * S2;

        G16 A, B;
        load16(A, 0, col, C);

        #pragma unroll 1
        for (int kt = 0; kt < S2; kt += 32) {
            int kg = kt >> 2;
            load16(B, kg + 4, col, C);
            if (isOut) process16<true >(A, Te, Tin, kD, kE, k0a, k1a, outp + kt);
            else       process16<false>(A, Te, Tin, kD, kE, k0a, k1a, nullptr);
            if (kt + 32 < S2) load16(A, kg + 8, col, C);
            if (isOut) process16<true >(B, Te, Tin, kD, kE, k0a, k1a, outp + kt + 16);
            else       process16<false>(B, Te, Tin, kD, kE, k0a, k1a, nullptr);
        }
    }
}

// ------------------------------------------- exact fallback (ragged n only)
__global__ void seq_kernel(const float* __restrict__ To, const float* __restrict__ Irr,
                           const float* __restrict__ Qint, const float* __restrict__ Qah,
                           const float* __restrict__ Ria,
                           const float* pR_ie, const float* pR_ea,
                           const float* pC_in, const float* pC_en,
                           const float* pA_si, const float* pA_se,
                           const float* pA_ii, const float* pA_ie,
                           const float* pTin0,
                           float* __restrict__ out, int n)
{
    float iRie = 1.0f / *pR_ie, iRea = 1.0f / *pR_ea;
    float invCin = 1.0f / *pC_in, invCen = 1.0f / *pC_en;
    float a_si = *pA_si, a_se = *pA_se, a_ii = *pA_ii, a_ie = *pA_ie;
    float M11  = 1.0f + DT_S * (iRea + iRie) * invCen;
    float nM12 = DT_S * iRie * invCen;
    float nM21 = DT_S * iRie * invCin;
    float Te = *pTin0, Tin = *pTin0;
    for (int t = 0; t < n; ++t) {
        float Ria_c = fmaxf(Ria[t], 1e-4f);
        float u     = 1.0f / Ria_c;
        float Qsol  = GA * fminf(fmaxf(Irr[t], 0.0f), 2000.0f);
        float qah   = fmaxf(Qah[t], 0.0f);
        float M22 = 1.0f + DT_S * (u + iRie) * invCin;
        float det = M11 * M22 - nM12 * nM21;
        float invdet = 1.0f / det;
        float b0 = To[t] * iRea * invCen + (a_se * Qsol + a_ie * Qint[t]) * invCen;
        float b1 = (To[t] * u + a_si * Qsol + a_ii * Qint[t] + qah) * invCin;
        float r0 = Te + DT_S * b0;
        float r1 = Tin + DT_S * b1;
        float Te_n  = (M22 * r0 + nM12 * r1) * invdet;
        float Tin_n = (M11 * r1 + nM21 * r0) * invdet;
        Tin_n = fminf(fmaxf(Tin_n, 5.0f), 45.0f);
        Te = Te_n; Tin = Tin_n;
        out[t] = Tin_n;
    }
}

extern "C" void kernel_launch(void* const* d_in, const int* in_sizes, int n_in,
                              void* d_out, int out_size)
{
    const float* pR_ie = (const float*)d_in[0];
    const float* pR_ea = (const float*)d_in[1];
    const float* pC_in = (const float*)d_in[2];
    const float* pC_en = (const float*)d_in[3];
    const float* pA_si = (const float*)d_in[4];
    const float* pA_se = (const float*)d_in[5];
    const float* pA_ii = (const float*)d_in[6];
    const float* pA_ie = (const float*)d_in[7];
    const float* pTin0 = (const float*)d_in[8];
    const float* To   = (const float*)d_in[9];
    const float* Irr  = (const float*)d_in[10];
    const float* Qint = (const float*)d_in[11];
    const float* Qah  = (const float*)d_in[12];
    const float* Ria  = (const float*)d_in[13];
    float* out = (float*)d_out;
    int n = in_sizes[9];

    if (n > NMAX || n <= 0 || (n % S2) != 0 || ((n / S2) % 128) != 0) {
        seq_kernel<<<1, 1>>>(To, Irr, Qint, Qah, Ria,
                             pR_ie, pR_ea, pC_in, pC_en,
                             pA_si, pA_se, pA_ii, pA_ie, pTin0, out, n);
        return;
    }

    int C = n / S2;                          // 16384
    dim3 pgrid(C / 32, S2 / 32);             // (512, 8) blocks of 256
    pre_t_kernel<<<pgrid, 256>>>(To, Irr, Qint, Qah, Ria,
                                 pR_ie, pR_ea, pC_in, pC_en,
                                 pA_si, pA_se, pA_ii, pA_ie, C);

    scan_t_kernel<<<C / 128, 128>>>(out, pR_ie, pR_ea, pC_in, pC_en, pTin0, C);
}